// round 1
// baseline (speedup 1.0000x reference)
#include <cuda_runtime.h>
#include <math.h>

// Problem: out = x + Re(IFFT2(ifftshift(fftshift(FFT2(x)) * gain)))
// x: [4,256,256,256] f32, angle_weights: [8] f32.
//
// Reductions:
//  * fftshift folded into gain indexing (gain at unshifted frequencies)
//  * only Hermitian-even part ge of the gain contributes to Re(.) for real x
//  * ge Hermitian => pack two real images into one complex FFT (512 FFT2s)
//  * DIF forward / DIT inverse => no bit-reversal passes; ge stored bit-reversed
//
// Scratch: 512 x 256 x 256 complex = 256 MiB static __device__ array.

#define NPAIR 512

__device__ float2 d_scratch[NPAIR * 256 * 256];   // 256 MiB
__device__ float  d_ge[256 * 256];                // even gain, [v_br][u_br] (transposed, bit-reversed)
__device__ float2 d_tw[128];                      // exp(-2*pi*i*j/256), j=0..127

// ---------------------------------------------------------------------------
// complex helpers
// ---------------------------------------------------------------------------
__device__ __forceinline__ float2 cmul(float2 a, float2 b) {
    return make_float2(a.x * b.x - a.y * b.y, a.x * b.y + a.y * b.x);
}

// ---------------------------------------------------------------------------
// gain at unshifted frequency (u,v) -- replicates the jnp f32 op sequence.
// jnp on GPU lowers atan2/sqrt/floor to libdevice, same as nvcc, so boundary
// pixels (axes/diagonals) round identically.
// ---------------------------------------------------------------------------
__device__ __forceinline__ float gain_at(int u, int v, const float* w) {
    float y = (float)(u < 128 ? u : u - 256);   // ((u+128)%256)-128
    float x = (float)(v < 128 ? v : v - 256);
    float r = sqrtf(y * y + x * x);
    if (!(r > 38.4f)) return 1.0f;              // HIGH_FREQ_RATIO * r_max = 0.3*128
    float theta = atan2f(y, x) + 3.14159265358979323846f;      // rounds to f32 pi
    float t = theta / 0.78539816339744830962f;                 // f32(2*pi/8)
    int k = (int)floorf(t);
    return w[k & 7];                            // t in [0,8] -> k in [0,8], mod 8
}

__global__ void k_init(const float* __restrict__ aw) {
    __shared__ float w[8];
    if (threadIdx.x < 8) w[threadIdx.x] = aw[threadIdx.x];
    __syncthreads();
    int u = blockIdx.x, v = threadIdx.x;
    float g1 = gain_at(u, v, w);
    float g2 = gain_at((256 - u) & 255, (256 - v) & 255, w);
    int ub = __brev((unsigned)u) >> 24;
    int vb = __brev((unsigned)v) >> 24;
    // transposed + bit-reversed so K2 reads it coalesced: d_ge[vb*256 + ub]
    d_ge[(vb << 8) | ub] = 0.5f * (g1 + g2);
    if (u == 0 && v < 128) {
        double ang = -2.0 * 3.14159265358979323846 * (double)v / 256.0;
        d_tw[v] = make_float2((float)cos(ang), (float)sin(ang));
    }
}

// ---------------------------------------------------------------------------
// 256-point FFTs in shared memory, 128 threads per transform.
// fft_dif: natural in -> bit-reversed out (forward, twiddles e^{-i...})
// fft_dit_inv: bit-reversed in -> natural out (inverse, conj twiddles, no 1/N)
// Both end each stage with __syncthreads(); all block threads must call.
// ---------------------------------------------------------------------------
__device__ __forceinline__ void fft_dif(float2* buf, const float2* tw, int t) {
#pragma unroll
    for (int s = 8; s >= 1; --s) {
        int half = 1 << (s - 1);
        int g = t >> (s - 1);
        int j = t & (half - 1);
        int i0 = (g << s) + j;
        int i1 = i0 + half;
        float2 a = buf[i0], b = buf[i1];
        float2 wv = tw[j << (8 - s)];
        buf[i0] = make_float2(a.x + b.x, a.y + b.y);
        float2 d = make_float2(a.x - b.x, a.y - b.y);
        buf[i1] = cmul(d, wv);
        __syncthreads();
    }
}

__device__ __forceinline__ void fft_dit_inv(float2* buf, const float2* tw, int t) {
#pragma unroll
    for (int s = 1; s <= 8; ++s) {
        int half = 1 << (s - 1);
        int g = t >> (s - 1);
        int j = t & (half - 1);
        int i0 = (g << s) + j;
        int i1 = i0 + half;
        float2 wv = tw[j << (8 - s)];
        wv.y = -wv.y;                       // conjugate for inverse
        float2 a = buf[i0];
        float2 b = cmul(buf[i1], wv);
        buf[i0] = make_float2(a.x + b.x, a.y + b.y);
        buf[i1] = make_float2(a.x - b.x, a.y - b.y);
        __syncthreads();
    }
}

// ---------------------------------------------------------------------------
// K1: pack two real images -> complex, forward FFT along W. 2 rows per block.
// ---------------------------------------------------------------------------
__global__ void __launch_bounds__(256) k_fft_rows(const float* __restrict__ x) {
    __shared__ float2 buf[2][256];
    __shared__ float2 tw[128];
    int tid = threadIdx.x;
    if (tid < 128) tw[tid] = d_tw[tid];
    int lr = tid >> 7;
    int t  = tid & 127;
    int bid = blockIdx.x;                       // 65536 blocks
    int p = bid >> 7;                           // pair index 0..511
    int r = ((bid & 127) << 1) | lr;            // row 0..255

    const float* xa = x + (((size_t)p) << 17) + ((size_t)r << 8);  // image 2p
    const float* xb = xa + 65536;                                   // image 2p+1
    buf[lr][t]       = make_float2(xa[t],       xb[t]);
    buf[lr][t + 128] = make_float2(xa[t + 128], xb[t + 128]);
    __syncthreads();

    fft_dif(buf[lr], tw, t);

    float2* o = d_scratch + (((size_t)p) << 16) + ((size_t)r << 8);
    o[t]       = buf[lr][t];
    o[t + 128] = buf[lr][t + 128];
}

// ---------------------------------------------------------------------------
// K2: forward FFT along H, multiply by ge (bit-reversed indices), inverse FFT
// along H. 4 storage-columns per block, 512 threads (128 per transform).
// ---------------------------------------------------------------------------
__global__ void __launch_bounds__(512) k_fft_cols() {
    __shared__ float2 cb[4][258];
    __shared__ float2 tw[128];
    int tid = threadIdx.x;
    if (tid < 128) tw[tid] = d_tw[tid];
    int p  = blockIdx.x >> 6;                   // pair
    int c0 = (blockIdx.x & 63) << 2;            // first of 4 storage columns
    float2* img = d_scratch + (((size_t)p) << 16);

#pragma unroll
    for (int e = tid; e < 1024; e += 512) {
        int row = e >> 2, col = e & 3;          // 32B-contiguous global reads
        cb[col][row] = img[(row << 8) + c0 + col];
    }
    __syncthreads();

    int col = tid >> 7;
    int t   = tid & 127;
    fft_dif(cb[col], tw, t);                    // ends with __syncthreads()

#pragma unroll
    for (int e = tid; e < 1024; e += 512) {     // coalesced d_ge reads
        int i = e & 255, c = e >> 8;
        float g = d_ge[((c0 + c) << 8) | i];
        cb[c][i].x *= g;
        cb[c][i].y *= g;
    }
    __syncthreads();

    fft_dit_inv(cb[col], tw, t);

#pragma unroll
    for (int e = tid; e < 1024; e += 512) {
        int row = e >> 2, c = e & 3;
        img[(row << 8) + c0 + c] = cb[c][row];
    }
}

// ---------------------------------------------------------------------------
// K3: inverse FFT along W, unpack Re/Im, scale 1/65536 (ortho fwd+inv), add x.
// ---------------------------------------------------------------------------
__global__ void __launch_bounds__(256) k_ifft_rows(const float* __restrict__ x,
                                                   float* __restrict__ out) {
    __shared__ float2 buf[2][256];
    __shared__ float2 tw[128];
    int tid = threadIdx.x;
    if (tid < 128) tw[tid] = d_tw[tid];
    int lr = tid >> 7;
    int t  = tid & 127;
    int bid = blockIdx.x;
    int p = bid >> 7;
    int r = ((bid & 127) << 1) | lr;

    const float2* sc = d_scratch + (((size_t)p) << 16) + ((size_t)r << 8);
    buf[lr][t]       = sc[t];
    buf[lr][t + 128] = sc[t + 128];
    __syncthreads();

    fft_dit_inv(buf[lr], tw, t);

    const float s = 1.0f / 65536.0f;
    size_t ia = (((size_t)p) << 17) + ((size_t)r << 8);
    const float* xa = x + ia;
    const float* xb = xa + 65536;
    float* oa = out + ia;
    float* ob = oa + 65536;
    float2 z0 = buf[lr][t];
    float2 z1 = buf[lr][t + 128];
    oa[t]       = xa[t]       + z0.x * s;
    ob[t]       = xb[t]       + z0.y * s;
    oa[t + 128] = xa[t + 128] + z1.x * s;
    ob[t + 128] = xb[t + 128] + z1.y * s;
}

// ---------------------------------------------------------------------------
extern "C" void kernel_launch(void* const* d_in, const int* in_sizes, int n_in,
                              void* d_out, int out_size) {
    (void)in_sizes; (void)n_in; (void)out_size;
    const float* x  = (const float*)d_in[0];
    const float* aw = (const float*)d_in[1];
    float* out = (float*)d_out;

    k_init<<<256, 256>>>(aw);
    k_fft_rows<<<65536, 256>>>(x);
    k_fft_cols<<<32768, 512>>>();
    k_ifft_rows<<<65536, 256>>>(x, out);
}

// round 2
// speedup vs baseline: 1.0997x; 1.0997x over previous
#include <cuda_runtime.h>
#include <math.h>

// out = x + Re(IFFT2(ifftshift(fftshift(FFT2(x)) * gain))), x: [4,256,256,256] f32.
//
// Round-2 architecture: 256-pt FFT = 16x16 Cooley-Tukey, both 16-pt FFTs in
// registers (16 threads/FFT, 16 float2 regs each); shared memory only for one
// 16x16 transpose per FFT (2 smem accesses/element vs 16 in radix-2 version).
// Intermediate spectra kept in digit-swapped storage order p=16t+j <-> k=16j+t;
// gain table precomputed in that order. W256 twiddles via register recurrence
// from a 16-entry base table.

#define NPAIR 512

__device__ __align__(16) float2 d_scratch[NPAIR * 256 * 256];   // 256 MiB
__device__ float  d_ge[256 * 256];    // even gain: d_ge[cs*256 + kh], kw = digitswap(cs)
__device__ float2 d_tw[16];           // W256^t = exp(-2*pi*i*t/256), t=0..15

// ---------------------------------------------------------------------------
__device__ __forceinline__ float2 cmul(float2 a, float2 b) {
    return make_float2(a.x * b.x - a.y * b.y, a.x * b.y + a.y * b.x);
}

// ---------------------------------------------------------------------------
// 16-point FFT fully in registers, natural order in and out.
// Forward twiddles e^{-2*pi*i/16}; INV=true uses conjugates (unnormalized).
// ---------------------------------------------------------------------------
template <bool INV>
__device__ __forceinline__ void fft16(float2 v[16]) {
    const float C1 = 0.92387953251128675613f;
    const float S1 = 0.38268343236508977173f;
    const float R2 = 0.70710678118654752440f;
    const float sg = INV ? 1.0f : -1.0f;
    const float2 W[8] = {
        { 1.0f, 0.0f }, {  C1, sg * S1 }, {  R2, sg * R2 }, {  S1, sg * C1 },
        { 0.0f, sg   }, { -S1, sg * C1 }, { -R2, sg * R2 }, { -C1, sg * S1 }
    };
#pragma unroll
    for (int s = 4; s >= 1; --s) {
        const int half = 1 << (s - 1);
#pragma unroll
        for (int g = 0; g < 16; g += 2 * half) {
#pragma unroll
            for (int j = 0; j < half; ++j) {
                const int i0 = g + j, i1 = i0 + half;
                float2 a = v[i0], b = v[i1];
                v[i0] = make_float2(a.x + b.x, a.y + b.y);
                float2 d = make_float2(a.x - b.x, a.y - b.y);
                v[i1] = cmul(d, W[j << (4 - s)]);
            }
        }
    }
    // bit-reverse permutation (compile-time register renaming)
    float2 tmp;
#define SWP(a, b) tmp = v[a]; v[a] = v[b]; v[b] = tmp;
    SWP(1, 8) SWP(2, 4) SWP(3, 12) SWP(5, 10) SWP(7, 14) SWP(11, 13)
#undef SWP
}

// apply v[k] *= base^k (k=0..15) via recurrence
__device__ __forceinline__ void twiddle_pow(float2 v[16], float2 base) {
    float2 w = base;
    v[1] = cmul(v[1], w);
#pragma unroll
    for (int k = 2; k < 16; ++k) {
        w = cmul(w, base);
        v[k] = cmul(v[k], w);
    }
}

// ---------------------------------------------------------------------------
// gain at unshifted frequency (u,v): identical f32 op sequence to jnp/libdevice.
// ---------------------------------------------------------------------------
__device__ __forceinline__ float gain_at(int u, int v, const float* w) {
    float y = (float)(u < 128 ? u : u - 256);
    float x = (float)(v < 128 ? v : v - 256);
    float r = sqrtf(y * y + x * x);
    if (!(r > 38.4f)) return 1.0f;                               // 0.3 * 128
    float theta = atan2f(y, x) + 3.14159265358979323846f;
    float t = theta / 0.78539816339744830962f;
    int k = (int)floorf(t);
    return w[k & 7];
}

__global__ void k_init(const float* __restrict__ aw) {
    __shared__ float w[8];
    if (threadIdx.x < 8) w[threadIdx.x] = aw[threadIdx.x];
    __syncthreads();
    int cs = blockIdx.x;                 // storage column (digit-swapped k_w)
    int kh = threadIdx.x;                // natural k_h
    int kw = ((cs & 15) << 4) | (cs >> 4);
    float g1 = gain_at(kh, kw, w);
    float g2 = gain_at((256 - kh) & 255, (256 - kw) & 255, w);
    d_ge[(cs << 8) | kh] = 0.5f * (g1 + g2);
    if (cs == 0 && kh < 16) {
        double ang = -2.0 * 3.14159265358979323846 * (double)kh / 256.0;
        d_tw[kh] = make_float2((float)cos(ang), (float)sin(ang));
    }
}

// ---------------------------------------------------------------------------
// K1: pack two real images -> complex; forward FFT along W.
// 16 rows/block, 16 threads/row. Output stored digit-swapped (p=16t+j).
// ---------------------------------------------------------------------------
__global__ void __launch_bounds__(256) k_fft_rows(const float* __restrict__ x) {
    __shared__ float2 xch[16 * 272];                 // slab/row, 16x16 pitch-17
    const int tid = threadIdx.x;
    const int f = tid >> 4;                          // row within block
    const int t = tid & 15;                          // FFT lane (n2 role)
    const int p = blockIdx.x >> 4;                   // pair 0..511
    const int r = ((blockIdx.x & 15) << 4) | f;      // row 0..255

    const float* xa = x + ((size_t)p << 17) + ((size_t)r << 8);
    const float* xb = xa + 65536;

    float2 v[16];
#pragma unroll
    for (int n1 = 0; n1 < 16; ++n1) {
        int idx = (n1 << 4) | t;
        v[n1] = make_float2(__ldg(xa + idx), __ldg(xb + idx));
    }
    fft16<false>(v);                                 // over n1 -> A_t[k1]
    twiddle_pow(v, d_tw[t]);                         // *= W256^{t*k1}

    float2* sl = xch + f * 272;
#pragma unroll
    for (int k1 = 0; k1 < 16; ++k1) sl[k1 * 17 + t] = v[k1];
    __syncthreads();
#pragma unroll
    for (int n2 = 0; n2 < 16; ++n2) v[n2] = sl[t * 17 + n2];

    fft16<false>(v);                                 // over n2 -> reg j = X[16j+t]

    float4* o4 = (float4*)(d_scratch + ((size_t)p << 16) + ((size_t)r << 8) + (t << 4));
#pragma unroll
    for (int j = 0; j < 16; j += 2)
        o4[j >> 1] = make_float4(v[j].x, v[j].y, v[j + 1].x, v[j + 1].y);
}

// ---------------------------------------------------------------------------
// K2: forward FFT along H, gain multiply, inverse FFT along H.
// 16 columns/block, 16 threads/column (c = tid&15 for coalescing).
// ---------------------------------------------------------------------------
__global__ void __launch_bounds__(256) k_fft_cols() {
    __shared__ float2 xch[16 * 257];                 // [k1*257 + t*16 + c]
    const int tid = threadIdx.x;
    const int c = tid & 15;
    const int t = tid >> 4;
    const int p  = blockIdx.x >> 4;
    const int c0 = (blockIdx.x & 15) << 4;

    float2* img = d_scratch + ((size_t)p << 16) + (c0 + c);

    float2 v[16];
#pragma unroll
    for (int n1 = 0; n1 < 16; ++n1) v[n1] = img[(size_t)((n1 << 4) | t) << 8];

    fft16<false>(v);                                 // over n1
    twiddle_pow(v, d_tw[t]);                         // *= W256^{t*k1}

#pragma unroll
    for (int k1 = 0; k1 < 16; ++k1) xch[k1 * 257 + t * 16 + c] = v[k1];
    __syncthreads();
#pragma unroll
    for (int n2 = 0; n2 < 16; ++n2) v[n2] = xch[t * 257 + n2 * 16 + c];

    fft16<false>(v);                                 // reg k2 = X[16k2 + t], k_h natural

    const float* ge = d_ge + ((c0 + c) << 8) + t;    // gain at (k_h = 16k2+t, col)
#pragma unroll
    for (int k2 = 0; k2 < 16; ++k2) {
        float g = __ldg(ge + (k2 << 4));
        v[k2].x *= g;
        v[k2].y *= g;
    }

    // inverse along H: thread already holds X[16k2 + t] in reg k2
    fft16<true>(v);                                  // over k2 -> B_t[n2]
    {   // *= W256^{-n2*t}
        float2 b = d_tw[t];
        b.y = -b.y;
        twiddle_pow(v, b);
    }
    __syncthreads();                                 // protect smem reuse (WAR)
#pragma unroll
    for (int n2 = 0; n2 < 16; ++n2) xch[n2 * 257 + t * 16 + c] = v[n2];
    __syncthreads();
#pragma unroll
    for (int k1 = 0; k1 < 16; ++k1) v[k1] = xch[t * 257 + k1 * 16 + c];

    fft16<true>(v);                                  // over k1 -> rows 16n1+t

#pragma unroll
    for (int n1 = 0; n1 < 16; ++n1) img[(size_t)((n1 << 4) | t) << 8] = v[n1];
}

// ---------------------------------------------------------------------------
// K3: inverse FFT along W (input digit-swapped, contiguous per thread),
// unpack Re/Im, scale 1/65536 (ortho fwd+inv), add x, store.
// ---------------------------------------------------------------------------
__global__ void __launch_bounds__(256) k_ifft_rows(const float* __restrict__ x,
                                                   float* __restrict__ out) {
    __shared__ float2 xch[16 * 272];
    const int tid = threadIdx.x;
    const int f = tid >> 4;
    const int t = tid & 15;
    const int p = blockIdx.x >> 4;
    const int r = ((blockIdx.x & 15) << 4) | f;

    const float4* s4 = (const float4*)(d_scratch + ((size_t)p << 16) + ((size_t)r << 8) + (t << 4));
    float2 v[16];
#pragma unroll
    for (int j = 0; j < 16; j += 2) {
        float4 q = __ldg(s4 + (j >> 1));
        v[j]     = make_float2(q.x, q.y);            // reg k2 = X[16k2 + t]
        v[j + 1] = make_float2(q.z, q.w);
    }

    fft16<true>(v);                                  // over k2 -> B_t[n2]
    {
        float2 b = d_tw[t];
        b.y = -b.y;
        twiddle_pow(v, b);                           // *= W256^{-n2*t}
    }

    float2* sl = xch + f * 272;
#pragma unroll
    for (int n2 = 0; n2 < 16; ++n2) sl[n2 * 17 + t] = v[n2];
    __syncthreads();
#pragma unroll
    for (int k1 = 0; k1 < 16; ++k1) v[k1] = sl[t * 17 + k1];

    fft16<true>(v);                                  // over k1 -> reg n1 = x[16n1+t]

    const float sc = 1.0f / 65536.0f;
    size_t ia = ((size_t)p << 17) + ((size_t)r << 8);
    const float* xa = x + ia;
    const float* xb = xa + 65536;
    float* oa = out + ia;
    float* ob = oa + 65536;
#pragma unroll
    for (int n1 = 0; n1 < 16; ++n1) {
        int idx = (n1 << 4) | t;
        oa[idx] = __ldg(xa + idx) + v[n1].x * sc;
        ob[idx] = __ldg(xb + idx) + v[n1].y * sc;
    }
}

// ---------------------------------------------------------------------------
extern "C" void kernel_launch(void* const* d_in, const int* in_sizes, int n_in,
                              void* d_out, int out_size) {
    (void)in_sizes; (void)n_in; (void)out_size;
    const float* x  = (const float*)d_in[0];
    const float* aw = (const float*)d_in[1];
    float* out = (float*)d_out;

    k_init<<<256, 256>>>(aw);
    k_fft_rows<<<8192, 256>>>(x);
    k_fft_cols<<<8192, 256>>>();
    k_ifft_rows<<<8192, 256>>>(x, out);
}